// round 4
// baseline (speedup 1.0000x reference)
#include <cuda_runtime.h>

#define NN 100000
#define EE 1600000
#define HH 64
#define GG 128
#define CC 10

// ---------------- scratch (device globals: no runtime allocation) ----------------
__device__ int   g_src[EE];
__device__ int   g_dst[EE];
__device__ float g_h1[(size_t)NN * HH];   // layer-1 transformed features
__device__ float g_h2[(size_t)NN * HH];   // layer-2 transformed features
__device__ float g_acc[(size_t)NN * HH];  // unnormalized weighted sum (reused per layer)
__device__ float g_e[EE];                 // per-edge logits (reused per layer)
__device__ float g_als[NN];
__device__ float g_ald[NN];
__device__ float g_m[NN];                 // segment max (init = self-loop logit)
__device__ float g_den[NN];               // unnormalized softmax denom (excl. self loop)
__device__ int   g_i64;                   // 1 if indices are int64, 0 if int32

__device__ __forceinline__ float lrelu(float x) { return x > 0.f ? x : 0.2f * x; }
__device__ __forceinline__ float elu_(float x)  { return x > 0.f ? x : expm1f(x); }

__device__ __forceinline__ void atomicMaxFloat(float* a, float v) {
    if (v >= 0.f) atomicMax((int*)a, __float_as_int(v));
    else          atomicMin((unsigned int*)a, __float_as_uint(v));
}

// ---------------- dtype detection: int64 indices have zero high words ----------------
__global__ void detect_kernel(const int* __restrict__ ei_w) {
    if (blockIdx.x == 0 && threadIdx.x == 0) {
        int flag = 1;
        for (int i = 0; i < 64; i++)
            if (ei_w[2 * i + 1] != 0) flag = 0;   // int32 data: odd words are real values
        g_i64 = flag;
    }
}

// ---------------- index conversion + output zeroing ----------------
__global__ void prep_kernel(const int* __restrict__ ei_w, float* __restrict__ out) {
    int i = blockIdx.x * blockDim.x + threadIdx.x;
    if (i < GG * CC) out[i] = 0.f;
    if (i < EE) {
        if (g_i64) {
            const long long* e64 = (const long long*)ei_w;
            g_src[i] = (int)e64[i];
            g_dst[i] = (int)e64[EE + i];
        } else {
            g_src[i] = ei_w[i];
            g_dst[i] = ei_w[EE + i];
        }
    }
}

// ---------------- GEMM (64x64) + GAT epilogue; mode 1 fuses layer-1 finalize ---------
// mode 0: input = xin (raw x).         writes g_h1.
// mode 1: input = elu(finalize(layer1)) from g_acc/g_h1/g_den/... . writes g_h2.
// Epilogue (both): al_s, al_d, m = lrelu(al_s+al_d) (self-loop logit), den = 0, acc = 0.
__global__ __launch_bounds__(128) void gemm_gat(
    int mode, const float* __restrict__ xin,
    const float* __restrict__ W, const float* __restrict__ avs,
    const float* __restrict__ avd, const float* __restrict__ bprev)
{
    __shared__ float4 Ws[64 * 16];
    __shared__ float as_s[64], ad_s[64], b_s[64];
    int tid = threadIdx.x;
    const float4* W4 = (const float4*)W;
    for (int i = tid; i < 64 * 16; i += 128) Ws[i] = W4[i];
    if (tid < 64) {
        as_s[tid] = avs[tid];
        ad_s[tid] = avd[tid];
        b_s[tid]  = mode ? bprev[tid] : 0.f;
    }
    __syncthreads();

    int row = blockIdx.x * 128 + tid;
    if (row >= NN) return;
    size_t base = (size_t)row * HH;

    float o[64];
#pragma unroll
    for (int c = 0; c < 64; c++) o[c] = 0.f;

    float exs = 0.f, inv = 0.f;
    if (mode) {
        float es = lrelu(g_als[row] + g_ald[row]);
        exs = __expf(es - g_m[row]);
        inv = 1.f / (g_den[row] + exs);
    }
    const float4* ap = (const float4*)(g_acc + base);
    const float4* hp = (const float4*)(g_h1 + base);
    const float4* xp = (const float4*)(xin + base);

#pragma unroll 4
    for (int k4 = 0; k4 < 16; k4++) {
        float xk[4];
        if (mode == 0) {
            float4 v = xp[k4];
            xk[0] = v.x; xk[1] = v.y; xk[2] = v.z; xk[3] = v.w;
        } else {
            float4 a = ap[k4];
            float4 h = hp[k4];
            xk[0] = elu_(fmaf(exs, h.x, a.x) * inv + b_s[4 * k4 + 0]);
            xk[1] = elu_(fmaf(exs, h.y, a.y) * inv + b_s[4 * k4 + 1]);
            xk[2] = elu_(fmaf(exs, h.z, a.z) * inv + b_s[4 * k4 + 2]);
            xk[3] = elu_(fmaf(exs, h.w, a.w) * inv + b_s[4 * k4 + 3]);
        }
#pragma unroll
        for (int kk = 0; kk < 4; kk++) {
            int k = 4 * k4 + kk;
            float xv = xk[kk];
#pragma unroll
            for (int c4 = 0; c4 < 16; c4++) {
                float4 w = Ws[k * 16 + c4];
                o[4 * c4 + 0] = fmaf(xv, w.x, o[4 * c4 + 0]);
                o[4 * c4 + 1] = fmaf(xv, w.y, o[4 * c4 + 1]);
                o[4 * c4 + 2] = fmaf(xv, w.z, o[4 * c4 + 2]);
                o[4 * c4 + 3] = fmaf(xv, w.w, o[4 * c4 + 3]);
            }
        }
    }

    // epilogue: write h row, attention halves, self-loop max init, zero den/acc
    float als = 0.f, ald = 0.f;
    float* hout = mode ? g_h2 : g_h1;
    float4* hop = (float4*)(hout + base);
    float4* aop = (float4*)(g_acc + base);
    float4 z = make_float4(0.f, 0.f, 0.f, 0.f);
#pragma unroll
    for (int c4 = 0; c4 < 16; c4++) {
        float4 v;
        v.x = o[4 * c4 + 0]; v.y = o[4 * c4 + 1];
        v.z = o[4 * c4 + 2]; v.w = o[4 * c4 + 3];
        hop[c4] = v;
        aop[c4] = z;
        als += v.x * as_s[4 * c4 + 0] + v.y * as_s[4 * c4 + 1]
             + v.z * as_s[4 * c4 + 2] + v.w * as_s[4 * c4 + 3];
        ald += v.x * ad_s[4 * c4 + 0] + v.y * ad_s[4 * c4 + 1]
             + v.z * ad_s[4 * c4 + 2] + v.w * ad_s[4 * c4 + 3];
    }
    g_als[row] = als;
    g_ald[row] = ald;
    g_m[row]   = lrelu(als + ald);   // self-loop logit seeds the segment max
    g_den[row] = 0.f;
}

// ---------------- edge pass A: logits + segment max ----------------
__global__ void edge_a() {
    int j = blockIdx.x * blockDim.x + threadIdx.x;
    if (j >= EE) return;
    int s = g_src[j], d = g_dst[j];
    float e = lrelu(g_als[s] + g_ald[d]);
    g_e[j] = e;
    atomicMaxFloat(&g_m[d], e);
}

// ---------------- edge pass B: exp + unnormalized weighted scatter (warp/edge) -------
__global__ void edge_b(int layer) {
    const float* __restrict__ h = layer ? g_h2 : g_h1;
    int t = blockIdx.x * blockDim.x + threadIdx.x;
    int j = t >> 5;
    int lane = t & 31;
    if (j >= EE) return;
    int s = g_src[j], d = g_dst[j];                 // warp-uniform loads (L1 broadcast)
    float ex = __expf(g_e[j] - g_m[d]);
    if (lane == 0) atomicAdd(&g_den[d], ex);
    size_t sb = (size_t)s * HH, db = (size_t)d * HH;
    float2 hv = *(const float2*)(h + sb + 2 * lane);
    atomicAdd(&g_acc[db + 2 * lane + 0], ex * hv.x);
    atomicAdd(&g_acc[db + 2 * lane + 1], ex * hv.y);
}

// ---------------- layer-2 finalize + MLP head + pooled output ----------------
__global__ __launch_bounds__(128) void final_kernel(
    const float* __restrict__ b2, const float* __restrict__ mw1,
    const float* __restrict__ mb1, const float* __restrict__ mw2,
    const float* __restrict__ mb2, const void* __restrict__ batch,
    float* __restrict__ out)
{
    __shared__ float mw1T[64 * 64];   // transposed: [j*64 + c]
    __shared__ float mw2s[64 * CC];
    __shared__ float mb1s[64], b2s[64], mb2s[CC];
    int tid = threadIdx.x;
    for (int i = tid; i < 64 * 64; i += 128) {
        int c = i >> 6, j = i & 63;
        mw1T[j * 64 + c] = mw1[i];
    }
    for (int i = tid; i < 64 * CC; i += 128) mw2s[i] = mw2[i];
    if (tid < 64) { mb1s[tid] = mb1[tid]; b2s[tid] = b2[tid]; }
    if (tid < CC) mb2s[tid] = mb2[tid];
    __syncthreads();

    int row = blockIdx.x * 128 + tid;
    int lane = tid & 31;
    bool active = row < NN;

    float o[CC];
#pragma unroll
    for (int c = 0; c < CC; c++) o[c] = 0.f;
    int g = 0;

    if (active) {
        size_t base = (size_t)row * HH;
        float es  = lrelu(g_als[row] + g_ald[row]);
        float exs = __expf(es - g_m[row]);
        float inv = 1.f / (g_den[row] + exs);
        float hf[64];
        const float4* ap = (const float4*)(g_acc + base);
        const float4* hp = (const float4*)(g_h2 + base);
#pragma unroll
        for (int i = 0; i < 16; i++) {
            float4 a = ap[i];
            float4 h = hp[i];
            hf[4 * i + 0] = elu_(fmaf(exs, h.x, a.x) * inv + b2s[4 * i + 0]);
            hf[4 * i + 1] = elu_(fmaf(exs, h.y, a.y) * inv + b2s[4 * i + 1]);
            hf[4 * i + 2] = elu_(fmaf(exs, h.z, a.z) * inv + b2s[4 * i + 2]);
            hf[4 * i + 3] = elu_(fmaf(exs, h.w, a.w) * inv + b2s[4 * i + 3]);
        }
#pragma unroll
        for (int c = 0; c < CC; c++) o[c] = mb2s[c];
        const float4* m1 = (const float4*)mw1T;
#pragma unroll 4
        for (int j = 0; j < 64; j++) {
            float t = mb1s[j];
#pragma unroll
            for (int c4 = 0; c4 < 16; c4++) {
                float4 w = m1[j * 16 + c4];
                t = fmaf(hf[4 * c4 + 0], w.x, t);
                t = fmaf(hf[4 * c4 + 1], w.y, t);
                t = fmaf(hf[4 * c4 + 2], w.z, t);
                t = fmaf(hf[4 * c4 + 3], w.w, t);
            }
            t = fmaxf(t, 0.f);
#pragma unroll
            for (int c = 0; c < CC; c++) o[c] = fmaf(t, mw2s[j * CC + c], o[c]);
        }
        if (g_i64) g = (int)((const long long*)batch)[row];
        else       g = ((const int*)batch)[row];
    }

    // batch is sorted -> most warps are graph-uniform: reduce in-warp, 1 atomic/col
    unsigned mask = 0xffffffffu;
    int g0 = __shfl_sync(mask, g, 0);
    bool uni = __all_sync(mask, g == g0);
    if (uni) {
#pragma unroll
        for (int c = 0; c < CC; c++) {
            float v = o[c];
#pragma unroll
            for (int off = 16; off > 0; off >>= 1) v += __shfl_xor_sync(mask, v, off);
            if (lane == 0) atomicAdd(&out[g0 * CC + c], v);
        }
    } else {
        if (active) {
#pragma unroll
            for (int c = 0; c < CC; c++) atomicAdd(&out[g * CC + c], o[c]);
        }
    }
}

// ---------------- launch ----------------
extern "C" void kernel_launch(void* const* d_in, const int* in_sizes, int n_in,
                              void* d_out, int out_size) {
    const float* x    = (const float*)d_in[0];
    const int*   ei_w = (const int*)d_in[1];     // int32 or int64 words; detected
    const void*  batch = d_in[2];
    const float* W1  = (const float*)d_in[3];
    const float* as1 = (const float*)d_in[4];
    const float* ad1 = (const float*)d_in[5];
    const float* b1  = (const float*)d_in[6];
    const float* W2  = (const float*)d_in[7];
    const float* as2 = (const float*)d_in[8];
    const float* ad2 = (const float*)d_in[9];
    const float* b2  = (const float*)d_in[10];
    const float* mw1 = (const float*)d_in[11];
    const float* mb1 = (const float*)d_in[12];
    const float* mw2 = (const float*)d_in[13];
    const float* mb2 = (const float*)d_in[14];
    float* out = (float*)d_out;

    int gb = (NN + 127) / 128;
    int eb = (EE + 255) / 256;
    long long et = (long long)EE * 32;
    int ebw = (int)((et + 255) / 256);

    detect_kernel<<<1, 32>>>(ei_w);
    prep_kernel<<<eb, 256>>>(ei_w, out);

    // layer 1
    gemm_gat<<<gb, 128>>>(0, x, W1, as1, ad1, b1);
    edge_a<<<eb, 256>>>();
    edge_b<<<ebw, 256>>>(0);

    // layer 2 (prologue finalizes layer 1)
    gemm_gat<<<gb, 128>>>(1, x, W2, as2, ad2, b1);
    edge_a<<<eb, 256>>>();
    edge_b<<<ebw, 256>>>(1);

    // finalize layer 2 + MLP + pool
    final_kernel<<<gb, 128>>>(b2, mw1, mb1, mw2, mb2, batch, out);
}

// round 5
// speedup vs baseline: 1.9952x; 1.9952x over previous
#include <cuda_runtime.h>

#define NN 100000
#define EE 1600000
#define HH 64
#define GG 128
#define CC 10
#define NB1 98   // ceil(NN/1024)

// ---------------- scratch (device globals: no runtime allocation) ----------------
__device__ int   g_src[EE];
__device__ int   g_dst[EE];
__device__ int   g_csrc[EE];
__device__ int   g_deg[NN];
__device__ int   g_rowptr[NN];
__device__ int   g_cursor[NN];
__device__ int   g_incl[NN];
__device__ int   g_bsum[NB1 + 1];
__device__ float g_h1[(size_t)NN * HH];   // pre-activation features (reused both layers)
__device__ float g_hx[(size_t)NN * HH];   // post softmax+bias+elu (reused both layers)
__device__ float g_als[NN];
__device__ float g_ald[NN];
__device__ int   g_i64;

__device__ __forceinline__ float lrelu(float x) { return x > 0.f ? x : 0.2f * x; }
__device__ __forceinline__ float elu_(float x)  { return x > 0.f ? x : expm1f(x); }

__global__ void detect_kernel(const int* __restrict__ ei_w) {
    if (threadIdx.x == 0) {
        int flag = 1;
        for (int i = 0; i < 64; i++)
            if (ei_w[2 * i + 1] != 0) flag = 0;
        g_i64 = flag;
    }
}

__global__ void zero_kernel(float* __restrict__ out) {
    int i = blockIdx.x * blockDim.x + threadIdx.x;
    if (i < NN) g_deg[i] = 0;
    if (i < GG * CC) out[i] = 0.f;
}

__global__ void prep_kernel(const int* __restrict__ ei_w) {
    int i = blockIdx.x * blockDim.x + threadIdx.x;
    if (i >= EE) return;
    int s, d;
    if (g_i64) {
        const long long* e64 = (const long long*)ei_w;
        s = (int)e64[i];
        d = (int)e64[EE + i];
    } else {
        s = ei_w[i];
        d = ei_w[EE + i];
    }
    g_src[i] = s;
    g_dst[i] = d;
    atomicAdd(&g_deg[d], 1);
}

__global__ void scan1_kernel() {
    __shared__ int sm[1024];
    int t = threadIdx.x;
    int i = blockIdx.x * 1024 + t;
    int v = (i < NN) ? g_deg[i] : 0;
    sm[t] = v;
    __syncthreads();
#pragma unroll
    for (int off = 1; off < 1024; off <<= 1) {
        int x = (t >= off) ? sm[t - off] : 0;
        __syncthreads();
        sm[t] += x;
        __syncthreads();
    }
    if (i < NN) g_incl[i] = sm[t];
    if (t == 1023) g_bsum[blockIdx.x] = sm[t];
}

__global__ void scan2_kernel() {
    if (threadIdx.x == 0) {
        int run = 0;
        for (int b = 0; b < NB1; b++) {
            int v = g_bsum[b];
            g_bsum[b] = run;
            run += v;
        }
    }
}

__global__ void scan3_kernel() {
    int i = blockIdx.x * blockDim.x + threadIdx.x;
    if (i >= NN) return;
    int excl = g_incl[i] - g_deg[i] + g_bsum[i >> 10];
    g_rowptr[i] = excl;
    g_cursor[i] = excl;
}

__global__ void fill_kernel() {
    int i = blockIdx.x * blockDim.x + threadIdx.x;
    if (i >= EE) return;
    int slot = atomicAdd(&g_cursor[g_dst[i]], 1);
    g_csrc[slot] = g_src[i];
}

// mode 0: read external x; mode 1: read g_hx
__global__ __launch_bounds__(128) void gemm_gat(
    int mode, const float* __restrict__ xext, const float* __restrict__ W,
    const float* __restrict__ avs, const float* __restrict__ avd)
{
    __shared__ float4 Ws[64 * 16];
    __shared__ float as_s[64], ad_s[64];
    int tid = threadIdx.x;
    const float4* W4 = (const float4*)W;
    for (int i = tid; i < 64 * 16; i += 128) Ws[i] = W4[i];
    if (tid < 64) { as_s[tid] = avs[tid]; ad_s[tid] = avd[tid]; }
    __syncthreads();

    int row = blockIdx.x * 128 + tid;
    if (row >= NN) return;
    size_t base = (size_t)row * HH;

    float o[64];
#pragma unroll
    for (int c = 0; c < 64; c++) o[c] = 0.f;

    const float* xin = mode ? g_hx : xext;
    const float4* xp = (const float4*)(xin + base);
#pragma unroll 4
    for (int k4 = 0; k4 < 16; k4++) {
        float4 v = xp[k4];
        float xk[4] = {v.x, v.y, v.z, v.w};
#pragma unroll
        for (int kk = 0; kk < 4; kk++) {
            int k = 4 * k4 + kk;
            float xv = xk[kk];
#pragma unroll
            for (int c4 = 0; c4 < 16; c4++) {
                float4 w = Ws[k * 16 + c4];
                o[4 * c4 + 0] = fmaf(xv, w.x, o[4 * c4 + 0]);
                o[4 * c4 + 1] = fmaf(xv, w.y, o[4 * c4 + 1]);
                o[4 * c4 + 2] = fmaf(xv, w.z, o[4 * c4 + 2]);
                o[4 * c4 + 3] = fmaf(xv, w.w, o[4 * c4 + 3]);
            }
        }
    }

    float als = 0.f, ald = 0.f;
    float4* hop = (float4*)(g_h1 + base);
#pragma unroll
    for (int c4 = 0; c4 < 16; c4++) {
        float4 v;
        v.x = o[4 * c4 + 0]; v.y = o[4 * c4 + 1];
        v.z = o[4 * c4 + 2]; v.w = o[4 * c4 + 3];
        hop[c4] = v;
        als += v.x * as_s[4 * c4 + 0] + v.y * as_s[4 * c4 + 1]
             + v.z * as_s[4 * c4 + 2] + v.w * as_s[4 * c4 + 3];
        ald += v.x * ad_s[4 * c4 + 0] + v.y * ad_s[4 * c4 + 1]
             + v.z * ad_s[4 * c4 + 2] + v.w * ad_s[4 * c4 + 3];
    }
    g_als[row] = als;
    g_ald[row] = ald;
}

// warp-per-dst gather: segment softmax + weighted sum + bias + elu, no atomics
__global__ __launch_bounds__(256) void gather_kernel(const float* __restrict__ bias) {
    __shared__ float bs[64];
    if (threadIdx.x < 64) bs[threadIdx.x] = bias[threadIdx.x];
    __syncthreads();

    int d = (blockIdx.x * 256 + threadIdx.x) >> 5;
    int lane = threadIdx.x & 31;
    if (d >= NN) return;

    const float* __restrict__ h = g_h1;
    const unsigned FULL = 0xffffffffu;
    float aldd = g_ald[d];
    float m_self = lrelu(g_als[d] + aldd);
    int row = g_rowptr[d];
    int deg = g_deg[d];
    size_t db = (size_t)d * HH;

    float2 hv0 = *(const float2*)(h + db + 2 * lane);
    float accx, accy, den, exs;

    if (deg <= 32) {
        int   s_l = 0;
        float e_l = -1e30f;
        if (lane < deg) {
            s_l = g_csrc[row + lane];
            e_l = lrelu(g_als[s_l] + aldd);
        }
        float m = fmaxf(m_self, e_l);
#pragma unroll
        for (int off = 16; off; off >>= 1) m = fmaxf(m, __shfl_xor_sync(FULL, m, off));
        float ex_l = (lane < deg) ? __expf(e_l - m) : 0.f;
        den = ex_l;
        exs = __expf(m_self - m);
        accx = exs * hv0.x;
        accy = exs * hv0.y;
        for (int k = 0; k < deg; k++) {
            float ex = __shfl_sync(FULL, ex_l, k);
            int   s  = __shfl_sync(FULL, s_l, k);
            float2 hv = *(const float2*)(h + (size_t)s * HH + 2 * lane);
            accx = fmaf(ex, hv.x, accx);
            accy = fmaf(ex, hv.y, accy);
        }
    } else {
        float m = m_self;
        for (int j = lane; j < deg; j += 32) {
            int s = g_csrc[row + j];
            m = fmaxf(m, lrelu(g_als[s] + aldd));
        }
#pragma unroll
        for (int off = 16; off; off >>= 1) m = fmaxf(m, __shfl_xor_sync(FULL, m, off));
        exs = __expf(m_self - m);
        accx = exs * hv0.x;
        accy = exs * hv0.y;
        den = 0.f;
        for (int base = 0; base < deg; base += 32) {
            int jl = base + lane;
            int s_l = 0; float ex_l = 0.f;
            if (jl < deg) {
                s_l = g_csrc[row + jl];
                ex_l = __expf(lrelu(g_als[s_l] + aldd) - m);
            }
            den += ex_l;
            int cnt = deg - base; if (cnt > 32) cnt = 32;
            if (cnt == 32) {
#pragma unroll
                for (int k = 0; k < 32; k++) {
                    float ex = __shfl_sync(FULL, ex_l, k);
                    int   s  = __shfl_sync(FULL, s_l, k);
                    float2 hv = *(const float2*)(h + (size_t)s * HH + 2 * lane);
                    accx = fmaf(ex, hv.x, accx);
                    accy = fmaf(ex, hv.y, accy);
                }
            } else {
                for (int k = 0; k < cnt; k++) {
                    float ex = __shfl_sync(FULL, ex_l, k);
                    int   s  = __shfl_sync(FULL, s_l, k);
                    float2 hv = *(const float2*)(h + (size_t)s * HH + 2 * lane);
                    accx = fmaf(ex, hv.x, accx);
                    accy = fmaf(ex, hv.y, accy);
                }
            }
        }
    }
#pragma unroll
    for (int off = 16; off; off >>= 1) den += __shfl_xor_sync(FULL, den, off);
    den += exs;   // self-loop term (warp-uniform)
    float inv = 1.f / den;
    float2 o;
    o.x = elu_(accx * inv + bs[2 * lane + 0]);
    o.y = elu_(accy * inv + bs[2 * lane + 1]);
    *(float2*)(g_hx + db + 2 * lane) = o;
}

__global__ __launch_bounds__(128) void final_kernel(
    const float* __restrict__ mw1, const float* __restrict__ mb1,
    const float* __restrict__ mw2, const float* __restrict__ mb2,
    const void* __restrict__ batch, float* __restrict__ out)
{
    __shared__ float mw1T[64 * 64];
    __shared__ float mw2s[64 * CC];
    __shared__ float mb1s[64], mb2s[CC];
    int tid = threadIdx.x;
    for (int i = tid; i < 64 * 64; i += 128) {
        int c = i >> 6, j = i & 63;
        mw1T[j * 64 + c] = mw1[i];
    }
    for (int i = tid; i < 64 * CC; i += 128) mw2s[i] = mw2[i];
    if (tid < 64) mb1s[tid] = mb1[tid];
    if (tid < CC) mb2s[tid] = mb2[tid];
    __syncthreads();

    int row = blockIdx.x * 128 + tid;
    int lane = tid & 31;
    bool active = row < NN;

    float o[CC];
#pragma unroll
    for (int c = 0; c < CC; c++) o[c] = 0.f;
    int g = 0;

    if (active) {
        size_t base = (size_t)row * HH;
        float hf[64];
        const float4* hp = (const float4*)(g_hx + base);
#pragma unroll
        for (int i = 0; i < 16; i++) {
            float4 h = hp[i];
            hf[4 * i + 0] = h.x; hf[4 * i + 1] = h.y;
            hf[4 * i + 2] = h.z; hf[4 * i + 3] = h.w;
        }
#pragma unroll
        for (int c = 0; c < CC; c++) o[c] = mb2s[c];
        const float4* m1 = (const float4*)mw1T;
#pragma unroll 4
        for (int j = 0; j < 64; j++) {
            float t = mb1s[j];
#pragma unroll
            for (int c4 = 0; c4 < 16; c4++) {
                float4 w = m1[j * 16 + c4];
                t = fmaf(hf[4 * c4 + 0], w.x, t);
                t = fmaf(hf[4 * c4 + 1], w.y, t);
                t = fmaf(hf[4 * c4 + 2], w.z, t);
                t = fmaf(hf[4 * c4 + 3], w.w, t);
            }
            t = fmaxf(t, 0.f);
#pragma unroll
            for (int c = 0; c < CC; c++) o[c] = fmaf(t, mw2s[j * CC + c], o[c]);
        }
        if (g_i64) g = (int)((const long long*)batch)[row];
        else       g = ((const int*)batch)[row];
    }

    unsigned mask = 0xffffffffu;
    int g0 = __shfl_sync(mask, g, 0);
    bool uni = __all_sync(mask, g == g0);
    if (uni) {
#pragma unroll
        for (int c = 0; c < CC; c++) {
            float v = o[c];
#pragma unroll
            for (int off = 16; off > 0; off >>= 1) v += __shfl_xor_sync(mask, v, off);
            if (lane == 0) atomicAdd(&out[g0 * CC + c], v);
        }
    } else {
        if (active) {
#pragma unroll
            for (int c = 0; c < CC; c++) atomicAdd(&out[g * CC + c], o[c]);
        }
    }
}

extern "C" void kernel_launch(void* const* d_in, const int* in_sizes, int n_in,
                              void* d_out, int out_size) {
    const float* x     = (const float*)d_in[0];
    const int*   ei_w  = (const int*)d_in[1];
    const void*  batch = d_in[2];
    const float* W1  = (const float*)d_in[3];
    const float* as1 = (const float*)d_in[4];
    const float* ad1 = (const float*)d_in[5];
    const float* b1  = (const float*)d_in[6];
    const float* W2  = (const float*)d_in[7];
    const float* as2 = (const float*)d_in[8];
    const float* ad2 = (const float*)d_in[9];
    const float* b2  = (const float*)d_in[10];
    const float* mw1 = (const float*)d_in[11];
    const float* mb1 = (const float*)d_in[12];
    const float* mw2 = (const float*)d_in[13];
    const float* mb2 = (const float*)d_in[14];
    float* out = (float*)d_out;

    int gb = (NN + 127) / 128;
    int nb = (NN + 255) / 256;
    int eb = (EE + 255) / 256;
    int wb = ((NN * 32) + 255) / 256;

    detect_kernel<<<1, 32>>>(ei_w);
    zero_kernel<<<nb, 256>>>(out);
    prep_kernel<<<eb, 256>>>(ei_w);
    scan1_kernel<<<NB1, 1024>>>();
    scan2_kernel<<<1, 32>>>();
    scan3_kernel<<<nb, 256>>>();
    fill_kernel<<<eb, 256>>>();

    gemm_gat<<<gb, 128>>>(0, x, W1, as1, ad1);
    gather_kernel<<<wb, 256>>>(b1);

    gemm_gat<<<gb, 128>>>(1, x, W2, as2, ad2);
    gather_kernel<<<wb, 256>>>(b2);

    final_kernel<<<gb, 128>>>(mw1, mb1, mw2, mb2, batch, out);
}